// round 1
// baseline (speedup 1.0000x reference)
#include <cuda_runtime.h>
#include <cstdint>

// Problem constants (fixed by the dataset problem)
#define Bg   16          // graphs
#define Nn   128         // nodes per graph
#define Mm   (Bg * Nn)   // 2048 total nodes
#define Dd   256         // hidden channels
#define TRI  ((Dd * (Dd + 1)) / 2)   // 32896 upper-tri elements per node
#define TRI4 (TRI / 4)               // 8224 float4 per node (TRI % 4 == 0)

// Device scratch (no allocations allowed)
__device__ float         g_s[Mm];        // per-node softmax weight
__device__ unsigned char g_rowtab[TRI];  // flat triu index -> row i (i < 256 fits u8)

// ---------------------------------------------------------------------------
// K0: build flat->row lookup. Row i occupies [off(i), off(i)+ (D-i)),
// off(i) = i*D - i*(i-1)/2. Cheap (32KB of writes), runs every launch.
// ---------------------------------------------------------------------------
__global__ void k_build_table() {
    int i = blockIdx.x;                       // 0..255
    int base = i * Dd - (i * (i - 1)) / 2;
    int len  = Dd - i;
    for (int t = threadIdx.x; t < len; t += blockDim.x)
        g_rowtab[base + t] = (unsigned char)i;
}

// ---------------------------------------------------------------------------
// K1: fused linear (D->1) + segment softmax. One block per graph.
// 1024 threads = 32 warps; each warp computes the dot product for 4 nodes
// (lanes read consecutive d -> fully coalesced 128B transactions).
// ---------------------------------------------------------------------------
__global__ __launch_bounds__(1024) void k_attn_softmax(
    const float* __restrict__ x, const float* __restrict__ W,
    const float* __restrict__ b)
{
    int g    = blockIdx.x;
    int tid  = threadIdx.x;
    int warp = tid >> 5;
    int lane = tid & 31;

    __shared__ float simp[Nn];
    __shared__ float red[2];

    // W into registers (broadcast across warps via L1)
    float wv[8];
#pragma unroll
    for (int u = 0; u < 8; u++) wv[u] = __ldg(&W[lane + 32 * u]);

#pragma unroll
    for (int nn = 0; nn < 4; nn++) {
        int node = warp * 4 + nn;                     // 0..127
        const float* xr = x + (size_t)(g * Nn + node) * Dd;
        float acc = 0.f;
#pragma unroll
        for (int u = 0; u < 8; u++) acc = fmaf(xr[lane + 32 * u], wv[u], acc);
#pragma unroll
        for (int o = 16; o; o >>= 1) acc += __shfl_xor_sync(0xffffffffu, acc, o);
        if (lane == 0) simp[node] = acc + b[0];
    }
    __syncthreads();

    if (warp == 0) {
        float v0 = simp[lane], v1 = simp[lane + 32],
              v2 = simp[lane + 64], v3 = simp[lane + 96];
        float mx = fmaxf(fmaxf(v0, v1), fmaxf(v2, v3));
#pragma unroll
        for (int o = 16; o; o >>= 1) mx = fmaxf(mx, __shfl_xor_sync(0xffffffffu, mx, o));
        float sum = __expf(v0 - mx) + __expf(v1 - mx) + __expf(v2 - mx) + __expf(v3 - mx);
        // NOTE: use expf (accurate) for the values actually stored; fast sum here is
        // consistent because we re-exp below with the same mx. Keep both expf for safety.
        sum = expf(v0 - mx) + expf(v1 - mx) + expf(v2 - mx) + expf(v3 - mx);
#pragma unroll
        for (int o = 16; o; o >>= 1) sum += __shfl_xor_sync(0xffffffffu, sum, o);
        if (lane == 0) { red[0] = mx; red[1] = sum; }
    }
    __syncthreads();

    float mx  = red[0];
    float inv = 1.0f / red[1];
    if (tid < Nn)
        g_s[g * Nn + tid] = expf(simp[tid] - mx) * inv;
}

// ---------------------------------------------------------------------------
// K2: the heavy kernel. One block per node (2048 blocks, 256 threads).
// Stage y = s * x_row in shared (1KB), then stream the 32896-element upper
// triangle as 8224 float4 stores. Row index i comes from the cached u8 table;
// column j is recovered arithmetically: off(i) = i*(513-i)/2, j = k - off + i.
// ---------------------------------------------------------------------------
__global__ __launch_bounds__(256) void k_sop(
    const float* __restrict__ x, float* __restrict__ out)
{
    int m   = blockIdx.x;
    int tid = threadIdx.x;

    __shared__ float y[Dd];

    float s = __ldg(&g_s[m]);
    y[tid]  = x[(size_t)m * Dd + tid] * s;
    __syncthreads();

    const uchar4* __restrict__ tab4 = (const uchar4*)g_rowtab;
    float4* __restrict__ out4 = (float4*)(out + (size_t)m * TRI);

    for (int k4 = tid; k4 < TRI4; k4 += 256) {
        uchar4 iv = __ldg(&tab4[k4]);
        int k = 4 * k4;

        int i0 = iv.x, i1 = iv.y, i2 = iv.z, i3 = iv.w;
        // j = k - i*(513-i)/2 + i
        int j0 = k     - ((i0 * (513 - i0)) >> 1) + i0;
        int j1 = k + 1 - ((i1 * (513 - i1)) >> 1) + i1;
        int j2 = k + 2 - ((i2 * (513 - i2)) >> 1) + i2;
        int j3 = k + 3 - ((i3 * (513 - i3)) >> 1) + i3;

        float4 r;
        r.x = y[i0] * y[j0];
        r.y = y[i1] * y[j1];
        r.z = y[i2] * y[j2];
        r.w = y[i3] * y[j3];
        out4[k4] = r;
    }
}

// ---------------------------------------------------------------------------
// Launch: inputs are [x, batch, edge, W, b]; batch/edge are inert.
// ---------------------------------------------------------------------------
extern "C" void kernel_launch(void* const* d_in, const int* in_sizes, int n_in,
                              void* d_out, int out_size)
{
    const float* x = (const float*)d_in[0];
    const float* W = (const float*)d_in[3];
    const float* b = (const float*)d_in[4];
    float* out = (float*)d_out;

    k_build_table<<<Dd, 128>>>();
    k_attn_softmax<<<Bg, 1024>>>(x, W, b);
    k_sop<<<Mm, 256>>>(x, out);
}

// round 4
// speedup vs baseline: 1.1686x; 1.1686x over previous
#include <cuda_runtime.h>
#include <cstdint>

#define Bg   16
#define Nn   128
#define Mm   (Bg * Nn)     // 2048 nodes
#define Dd   256
#define TRI  ((Dd * (Dd + 1)) / 2)   // 32896
#define TRI4 (TRI / 4)               // 8224

__device__ float         g_s[Mm];        // per-node softmax weight
__device__ unsigned char g_rowtab[TRI];  // flat triu index -> row i

// row start offset: start(i) = i*(513-i)/2
__device__ __forceinline__ int row_start(int i) { return (i * (513 - i)) >> 1; }

// ---------------------------------------------------------------------------
// K1: fused (a) linear D->1 + segment softmax  (b) triu row-lookup table build
// One block per graph, 1024 threads.
// ---------------------------------------------------------------------------
__global__ __launch_bounds__(1024) void k_attn_softmax(
    const float* __restrict__ x, const float* __restrict__ W,
    const float* __restrict__ b)
{
    int g    = blockIdx.x;
    int tid  = threadIdx.x;
    int warp = tid >> 5;
    int lane = tid & 31;

    __shared__ float simp[Nn];
    __shared__ float red[2];

    // ---- table build (independent work, grid-stride across 16 blocks) ----
    {
        int gt = g * 1024 + tid;
        for (int t = gt; t < TRI; t += Bg * 1024) {
            // i = floor((513 - sqrt(513^2 - 8t)) / 2); exact after integer fixup
            int disc = 263169 - 8 * t;
            int i = (int)(0.5f * (513.0f - sqrtf((float)disc)));
            if (row_start(i + 1) <= t) i++;
            if (row_start(i) > t)      i--;
            g_rowtab[t] = (unsigned char)i;
        }
    }

    // ---- attention dot products: warp handles 4 nodes ----
    float wv[8];
#pragma unroll
    for (int u = 0; u < 8; u++) wv[u] = __ldg(&W[lane + 32 * u]);

#pragma unroll
    for (int nn = 0; nn < 4; nn++) {
        int node = warp * 4 + nn;
        const float* xr = x + (size_t)(g * Nn + node) * Dd;
        float acc = 0.f;
#pragma unroll
        for (int u = 0; u < 8; u++) acc = fmaf(xr[lane + 32 * u], wv[u], acc);
#pragma unroll
        for (int o = 16; o; o >>= 1) acc += __shfl_xor_sync(0xffffffffu, acc, o);
        if (lane == 0) simp[node] = acc + b[0];
    }
    __syncthreads();

    if (warp == 0) {
        float v0 = simp[lane], v1 = simp[lane + 32],
              v2 = simp[lane + 64], v3 = simp[lane + 96];
        float mx = fmaxf(fmaxf(v0, v1), fmaxf(v2, v3));
#pragma unroll
        for (int o = 16; o; o >>= 1) mx = fmaxf(mx, __shfl_xor_sync(0xffffffffu, mx, o));
        float sum = expf(v0 - mx) + expf(v1 - mx) + expf(v2 - mx) + expf(v3 - mx);
#pragma unroll
        for (int o = 16; o; o >>= 1) sum += __shfl_xor_sync(0xffffffffu, sum, o);
        if (lane == 0) { red[0] = mx; red[1] = sum; }
    }
    __syncthreads();

    if (tid < Nn)
        g_s[g * Nn + tid] = expf(simp[tid] - red[0]) * (1.0f / red[1]);
}

// ---------------------------------------------------------------------------
// K2: per-node outer-product triu stream. One block per node, 256 threads.
//
// Conflict-free trick: keep 4 phase-shifted float4 images of y in shared:
//   z[c][q] = { y[4q+c], y[4q+c+1], y[4q+c+2], y[4q+c+3] }
// Within a row the group phase p = j0 & 3 is constant, so the 4 consecutive
// y[j] values come from ONE conflict-free LDS.128 at z[p][j0>>2].
// Row-crossing groups (i3 != i0) get exact per-element fixup (rare).
// ---------------------------------------------------------------------------
__global__ __launch_bounds__(256) void k_sop(
    const float* __restrict__ x, float* __restrict__ out)
{
    int m   = blockIdx.x;
    int tid = threadIdx.x;

    __shared__ float  y[Dd + 4];     // padded: window may read y[255+3]
    __shared__ float4 z[4][68];      // 68 > 64 to pad row stride

    float s = __ldg(&g_s[m]);
    y[tid]  = x[(size_t)m * Dd + tid] * s;
    if (tid < 4) y[Dd + tid] = 0.0f;
    __syncthreads();

    {   // build phase-shifted images: 256 threads -> 4*64 float4 writes
        int c = tid >> 6;            // 0..3
        int q = tid & 63;            // 0..63
        int base = 4 * q + c;        // max 255 (+3 pad ok)
        z[c][q] = make_float4(y[base], y[base + 1], y[base + 2], y[base + 3]);
    }
    __syncthreads();

    const uchar4* __restrict__ tab4 = (const uchar4*)g_rowtab;
    float4* __restrict__ out4 = (float4*)(out + (size_t)m * TRI);

    for (int k4 = tid; k4 < TRI4; k4 += 256) {
        uchar4 iv = __ldg(&tab4[k4]);
        int k  = 4 * k4;
        int i0 = iv.x, i3 = iv.w;

        int j0 = k - row_start(i0) + i0;      // column of first element
        int p  = j0 & 3;
        int q  = j0 >> 2;

        float4 w  = z[p][q];                  // y[j0 .. j0+3], 1x LDS.128
        float yi0 = y[i0];

        float4 r;
        r.x = yi0 * w.x;
        r.y = yi0 * w.y;
        r.z = yi0 * w.z;
        r.w = yi0 * w.w;

        if (i3 != i0) {                       // group crosses row boundary
            int i1 = iv.y, i2 = iv.z;
            r.y = y[i1] * y[k + 1 - row_start(i1) + i1];
            r.z = y[i2] * y[k + 2 - row_start(i2) + i2];
            r.w = y[i3] * y[k + 3 - row_start(i3) + i3];
        }
        __stcs(&out4[k4], r);                 // streaming store: don't pollute L2
    }
}

// ---------------------------------------------------------------------------
extern "C" void kernel_launch(void* const* d_in, const int* in_sizes, int n_in,
                              void* d_out, int out_size)
{
    const float* x = (const float*)d_in[0];
    const float* W = (const float*)d_in[3];
    const float* b = (const float*)d_in[4];
    float* out = (float*)d_out;

    k_attn_softmax<<<Bg, 1024>>>(x, W, b);
    k_sop<<<Mm, 256>>>(x, out);
}